// round 5
// baseline (speedup 1.0000x reference)
#include <cuda_runtime.h>
#include <math.h>

#define NUM_SEQS   64
#define NUM_HEADS  32
#define KVH        8
#define GQ         4      // query heads per kv head
#define HD         128    // head size
#define BS         16     // paged block size
#define MAXL       2048
#define MAXB       128    // max blocks per seq
#define PART       128    // tokens per split-KV partition
#define NP         (MAXL / PART)   // 16
#define NTHREADS   256
#define NWARPS     8

// Split-KV scratch (device globals)
__device__ float g_pacc[NUM_SEQS * KVH * NP * GQ * HD];
__device__ float g_pl[NUM_SEQS * KVH * NP * GQ];

__global__ __launch_bounds__(NTHREADS)
void paged_attn_part_kernel(const float* __restrict__ q,
                            const float* __restrict__ kcache,
                            const float* __restrict__ vcache,
                            const float* __restrict__ scale_p,
                            const int*   __restrict__ btab,
                            const int*   __restrict__ seqlen,
                            const float* __restrict__ slopes)
{
    const int p    = blockIdx.x % NP;
    const int kv   = (blockIdx.x / NP) % KVH;
    const int s    = blockIdx.x / (NP * KVH);
    const int tid  = threadIdx.x;
    const int lane = tid & 31;
    const int warp = tid >> 5;

    const int len = seqlen[s];
    const int t0  = p * PART;
    if (t0 >= len) return;
    const int tmax = min(PART, len - t0);
    const float scale = scale_p[0];

    __shared__ float red[NWARPS][GQ][HD];   // 16 KB; stages Q at start
    __shared__ float wl[NWARPS][GQ];        // per-warp prob sums
    __shared__ int   blk[PART / BS];

    // Stage Q (scaled)
    for (int i = tid; i < GQ * HD; i += NTHREADS)
        red[0][0][i] = q[(s * NUM_HEADS + kv * GQ) * HD + i] * scale;
    const int nblk = (tmax + BS - 1) >> 4;
    if (tid < nblk) blk[tid] = btab[s * MAXB + (t0 >> 4) + tid];
    __syncthreads();

    const float4 qr0 = ((const float4*)&red[0][0][0])[lane];
    const float4 qr1 = ((const float4*)&red[0][1][0])[lane];
    const float4 qr2 = ((const float4*)&red[0][2][0])[lane];
    const float4 qr3 = ((const float4*)&red[0][3][0])[lane];
    __syncthreads();   // Q consumed; red reused for output reduction

    const float slp0 = slopes[kv * GQ + 0];
    const float slp1 = slopes[kv * GQ + 1];
    const float slp2 = slopes[kv * GQ + 2];
    const float slp3 = slopes[kv * GQ + 3];
    const float relbase = (float)(t0 - (len - 1));

    const size_t kvbase   = (size_t)kv * BS * HD;
    const size_t kvstride = (size_t)KVH * BS * HD;

    float4 a0 = {0,0,0,0}, a1 = {0,0,0,0}, a2 = {0,0,0,0}, a3 = {0,0,0,0};
    float l0 = 0.f, l1 = 0.f, l2 = 0.f, l3 = 0.f;

    // Fused, barrier-free main loop: warp owns tokens tl = warp + 8j.
    // Loads are unconditional (token index clamped to a valid row) and
    // streaming (__ldcs) so KV doesn't thrash L2; invalid tokens are
    // masked by multiplying the exp weight with 0.
    #pragma unroll
    for (int jb = 0; jb < 16; jb += 2) {
        const int tlA = warp + jb * NWARPS;
        const int tlB = tlA + NWARPS;
        const int tcA = min(tlA, tmax - 1);
        const int tcB = min(tlB, tmax - 1);

        const size_t rowA = (size_t)blk[tcA >> 4] * kvstride + kvbase
                          + (size_t)(tcA & 15) * HD;
        const size_t rowB = (size_t)blk[tcB >> 4] * kvstride + kvbase
                          + (size_t)(tcB & 15) * HD;
        const float4 kA = __ldcs(((const float4*)(kcache + rowA)) + lane);
        const float4 vA = __ldcs(((const float4*)(vcache + rowA)) + lane);
        const float4 kB = __ldcs(((const float4*)(kcache + rowB)) + lane);
        const float4 vB = __ldcs(((const float4*)(vcache + rowB)) + lane);

        const float validA = (tlA < tmax) ? 1.0f : 0.0f;
        const float validB = (tlB < tmax) ? 1.0f : 0.0f;

        {
            float p0 = qr0.x*kA.x + qr0.y*kA.y + qr0.z*kA.z + qr0.w*kA.w;
            float p1 = qr1.x*kA.x + qr1.y*kA.y + qr1.z*kA.z + qr1.w*kA.w;
            float p2 = qr2.x*kA.x + qr2.y*kA.y + qr2.z*kA.z + qr2.w*kA.w;
            float p3 = qr3.x*kA.x + qr3.y*kA.y + qr3.z*kA.z + qr3.w*kA.w;
            #pragma unroll
            for (int off = 16; off > 0; off >>= 1) {
                p0 += __shfl_xor_sync(0xffffffff, p0, off);
                p1 += __shfl_xor_sync(0xffffffff, p1, off);
                p2 += __shfl_xor_sync(0xffffffff, p2, off);
                p3 += __shfl_xor_sync(0xffffffff, p3, off);
            }
            const float rel = relbase + (float)tlA;
            const float e0 = __expf(p0 + slp0 * rel) * validA;
            const float e1 = __expf(p1 + slp1 * rel) * validA;
            const float e2 = __expf(p2 + slp2 * rel) * validA;
            const float e3 = __expf(p3 + slp3 * rel) * validA;
            l0 += e0; l1 += e1; l2 += e2; l3 += e3;
            a0.x += e0*vA.x; a0.y += e0*vA.y; a0.z += e0*vA.z; a0.w += e0*vA.w;
            a1.x += e1*vA.x; a1.y += e1*vA.y; a1.z += e1*vA.z; a1.w += e1*vA.w;
            a2.x += e2*vA.x; a2.y += e2*vA.y; a2.z += e2*vA.z; a2.w += e2*vA.w;
            a3.x += e3*vA.x; a3.y += e3*vA.y; a3.z += e3*vA.z; a3.w += e3*vA.w;
        }
        {
            float p0 = qr0.x*kB.x + qr0.y*kB.y + qr0.z*kB.z + qr0.w*kB.w;
            float p1 = qr1.x*kB.x + qr1.y*kB.y + qr1.z*kB.z + qr1.w*kB.w;
            float p2 = qr2.x*kB.x + qr2.y*kB.y + qr2.z*kB.z + qr2.w*kB.w;
            float p3 = qr3.x*kB.x + qr3.y*kB.y + qr3.z*kB.z + qr3.w*kB.w;
            #pragma unroll
            for (int off = 16; off > 0; off >>= 1) {
                p0 += __shfl_xor_sync(0xffffffff, p0, off);
                p1 += __shfl_xor_sync(0xffffffff, p1, off);
                p2 += __shfl_xor_sync(0xffffffff, p2, off);
                p3 += __shfl_xor_sync(0xffffffff, p3, off);
            }
            const float rel = relbase + (float)tlB;
            const float e0 = __expf(p0 + slp0 * rel) * validB;
            const float e1 = __expf(p1 + slp1 * rel) * validB;
            const float e2 = __expf(p2 + slp2 * rel) * validB;
            const float e3 = __expf(p3 + slp3 * rel) * validB;
            l0 += e0; l1 += e1; l2 += e2; l3 += e3;
            a0.x += e0*vB.x; a0.y += e0*vB.y; a0.z += e0*vB.z; a0.w += e0*vB.w;
            a1.x += e1*vB.x; a1.y += e1*vB.y; a1.z += e1*vB.z; a1.w += e1*vB.w;
            a2.x += e2*vB.x; a2.y += e2*vB.y; a2.z += e2*vB.z; a2.w += e2*vB.w;
            a3.x += e3*vB.x; a3.y += e3*vB.y; a3.z += e3*vB.z; a3.w += e3*vB.w;
        }
    }

    // Cross-warp reduction
    if (lane == 0) { wl[warp][0] = l0; wl[warp][1] = l1; wl[warp][2] = l2; wl[warp][3] = l3; }
    ((float4*)&red[warp][0][0])[lane] = a0;
    ((float4*)&red[warp][1][0])[lane] = a1;
    ((float4*)&red[warp][2][0])[lane] = a2;
    ((float4*)&red[warp][3][0])[lane] = a3;
    __syncthreads();

    const int d  = tid & 127;
    const int g0 = tid >> 7;
    float r0 = 0.f, r1 = 0.f;
    #pragma unroll
    for (int w = 0; w < NWARPS; w++) {
        r0 += red[w][g0][d];
        r1 += red[w][g0 + 2][d];
    }

    const size_t pb = ((size_t)(s * KVH + kv) * NP + p) * GQ;
    g_pacc[(pb + g0)     * HD + d] = r0;
    g_pacc[(pb + g0 + 2) * HD + d] = r1;
    if (tid < GQ) {
        float L = 0.f;
        #pragma unroll
        for (int w = 0; w < NWARPS; w++) L += wl[w][tid];
        g_pl[pb + tid] = L;
    }
}

// Reduce: 512 threads = 16 warps = 4 heads x 4 partition-chunks.
// Warp (g, c) sums partitions p = c, c+4, c+8, c+12; smem tree combine.
__global__ __launch_bounds__(512)
void paged_attn_reduce_kernel(const int* __restrict__ seqlen,
                              float* __restrict__ out)
{
    const int s    = blockIdx.x / KVH;
    const int kv   = blockIdx.x % KVH;
    const int wid  = threadIdx.x >> 5;
    const int lane = threadIdx.x & 31;
    const int g    = wid & 3;              // head within group
    const int c    = wid >> 2;             // partition chunk 0..3

    __shared__ float4 so[4][GQ][32];
    __shared__ float  sl[4][GQ];

    const int len = seqlen[s];
    const int np  = (len + PART - 1) / PART;
    const size_t base = (size_t)(s * KVH + kv) * NP * GQ;

    float4 o = {0,0,0,0};
    float  L = 0.f;
    for (int p = c; p < np; p += 4) {
        const size_t idx = base + (size_t)p * GQ + g;
        const float4 a = ((const float4*)g_pacc)[idx * (HD/4) + lane];
        L += g_pl[idx];
        o.x += a.x; o.y += a.y; o.z += a.z; o.w += a.w;
    }
    so[c][g][lane] = o;
    if (lane == 0) sl[c][g] = L;
    __syncthreads();

    if (wid < GQ) {
        const int gg = wid;
        float4 r = so[0][gg][lane];
        const float4 r1 = so[1][gg][lane];
        const float4 r2 = so[2][gg][lane];
        const float4 r3 = so[3][gg][lane];
        r.x += r1.x + r2.x + r3.x;
        r.y += r1.y + r2.y + r3.y;
        r.z += r1.z + r2.z + r3.z;
        r.w += r1.w + r2.w + r3.w;
        const float inv = 1.0f / (sl[0][gg] + sl[1][gg] + sl[2][gg] + sl[3][gg]);
        r.x *= inv; r.y *= inv; r.z *= inv; r.w *= inv;
        ((float4*)out)[(size_t)(s * NUM_HEADS + kv * GQ + gg) * (HD/4) + lane] = r;
    }
}

extern "C" void kernel_launch(void* const* d_in, const int* in_sizes, int n_in,
                              void* d_out, int out_size) {
    const float* query       = (const float*)d_in[0];
    const float* key_cache   = (const float*)d_in[1];
    const float* value_cache = (const float*)d_in[2];
    const float* scale       = (const float*)d_in[4];
    const int*   block_tab   = (const int*)  d_in[5];
    const int*   seq_lens    = (const int*)  d_in[6];
    const float* alibi       = (const float*)d_in[9];
    float* out = (float*)d_out;

    paged_attn_part_kernel<<<NUM_SEQS * KVH * NP, NTHREADS>>>(
        query, key_cache, value_cache, scale, block_tab, seq_lens, alibi);
    paged_attn_reduce_kernel<<<NUM_SEQS * KVH, 512>>>(seq_lens, out);
}

// round 6
// speedup vs baseline: 1.0248x; 1.0248x over previous
#include <cuda_runtime.h>
#include <math.h>

#define NUM_SEQS   64
#define NUM_HEADS  32
#define KVH        8
#define GQ         4      // query heads per kv head
#define HD         128    // head size
#define BS         16     // paged block size
#define MAXL       2048
#define MAXB       128    // max blocks per seq
#define PART       128    // tokens per split-KV partition
#define NP         (MAXL / PART)   // 16
#define NTHREADS   256
#define NWARPS     8

// Cross-partition accumulators (combine is a plain sum: no per-partition max)
__device__ float g_oacc[NUM_SEQS * NUM_HEADS * HD];   // 1 MB
__device__ float g_ol[NUM_SEQS * NUM_HEADS];

__global__ __launch_bounds__(NTHREADS)
void zero_acc_kernel()
{
    const int i = blockIdx.x * NTHREADS + threadIdx.x;
    if (i < NUM_SEQS * NUM_HEADS * HD) g_oacc[i] = 0.0f;
    if (i < NUM_SEQS * NUM_HEADS)      g_ol[i]   = 0.0f;
}

__global__ __launch_bounds__(NTHREADS)
void paged_attn_part_kernel(const float* __restrict__ q,
                            const float* __restrict__ kcache,
                            const float* __restrict__ vcache,
                            const float* __restrict__ scale_p,
                            const int*   __restrict__ btab,
                            const int*   __restrict__ seqlen,
                            const float* __restrict__ slopes)
{
    const int p    = blockIdx.x % NP;
    const int kv   = (blockIdx.x / NP) % KVH;
    const int s    = blockIdx.x / (NP * KVH);
    const int tid  = threadIdx.x;
    const int lane = tid & 31;
    const int warp = tid >> 5;

    const int len = seqlen[s];
    const int t0  = p * PART;
    if (t0 >= len) return;
    const int tmax = min(PART, len - t0);
    const float scale = scale_p[0];

    __shared__ float red[NWARPS][GQ][HD];   // 16 KB; stages Q at start
    __shared__ float wl[NWARPS][GQ];        // per-warp prob sums
    __shared__ int   blk[PART / BS];

    // Stage Q (scaled)
    for (int i = tid; i < GQ * HD; i += NTHREADS)
        red[0][0][i] = q[(s * NUM_HEADS + kv * GQ) * HD + i] * scale;
    const int nblk = (tmax + BS - 1) >> 4;
    if (tid < nblk) blk[tid] = btab[s * MAXB + (t0 >> 4) + tid];
    __syncthreads();

    const float4 qr0 = ((const float4*)&red[0][0][0])[lane];
    const float4 qr1 = ((const float4*)&red[0][1][0])[lane];
    const float4 qr2 = ((const float4*)&red[0][2][0])[lane];
    const float4 qr3 = ((const float4*)&red[0][3][0])[lane];
    __syncthreads();   // Q consumed; red reused for output reduction

    const float slp0 = slopes[kv * GQ + 0];
    const float slp1 = slopes[kv * GQ + 1];
    const float slp2 = slopes[kv * GQ + 2];
    const float slp3 = slopes[kv * GQ + 3];
    const float relbase = (float)(t0 - (len - 1));

    const size_t kvbase   = (size_t)kv * BS * HD;
    const size_t kvstride = (size_t)KVH * BS * HD;

    float4 a0 = {0,0,0,0}, a1 = {0,0,0,0}, a2 = {0,0,0,0}, a3 = {0,0,0,0};
    float l0 = 0.f, l1 = 0.f, l2 = 0.f, l3 = 0.f;

    // Fused, barrier-free main loop: warp owns tokens tl = warp + 8j.
    // 4 tokens per iteration: all 8 loads (K+V) issued before any compute.
    #pragma unroll
    for (int jb = 0; jb < 16; jb += 4) {
        int   tl[4];
        bool  ok[4];
        float4 kk[4], vv[4];
        #pragma unroll
        for (int u = 0; u < 4; u++) {
            tl[u] = warp + (jb + u) * NWARPS;
            ok[u] = tl[u] < tmax;
            if (ok[u]) {
                const size_t row = (size_t)blk[tl[u] >> 4] * kvstride + kvbase
                                 + (size_t)(tl[u] & 15) * HD;
                kk[u] = ((const float4*)(kcache + row))[lane];
                vv[u] = ((const float4*)(vcache + row))[lane];
            }
        }
        #pragma unroll
        for (int u = 0; u < 4; u++) {
            if (ok[u]) {
                float p0 = qr0.x*kk[u].x + qr0.y*kk[u].y + qr0.z*kk[u].z + qr0.w*kk[u].w;
                float p1 = qr1.x*kk[u].x + qr1.y*kk[u].y + qr1.z*kk[u].z + qr1.w*kk[u].w;
                float p2 = qr2.x*kk[u].x + qr2.y*kk[u].y + qr2.z*kk[u].z + qr2.w*kk[u].w;
                float p3 = qr3.x*kk[u].x + qr3.y*kk[u].y + qr3.z*kk[u].z + qr3.w*kk[u].w;
                #pragma unroll
                for (int off = 16; off > 0; off >>= 1) {
                    p0 += __shfl_xor_sync(0xffffffff, p0, off);
                    p1 += __shfl_xor_sync(0xffffffff, p1, off);
                    p2 += __shfl_xor_sync(0xffffffff, p2, off);
                    p3 += __shfl_xor_sync(0xffffffff, p3, off);
                }
                const float rel = relbase + (float)tl[u];
                const float e0 = __expf(p0 + slp0 * rel);
                const float e1 = __expf(p1 + slp1 * rel);
                const float e2 = __expf(p2 + slp2 * rel);
                const float e3 = __expf(p3 + slp3 * rel);
                l0 += e0; l1 += e1; l2 += e2; l3 += e3;
                a0.x += e0*vv[u].x; a0.y += e0*vv[u].y; a0.z += e0*vv[u].z; a0.w += e0*vv[u].w;
                a1.x += e1*vv[u].x; a1.y += e1*vv[u].y; a1.z += e1*vv[u].z; a1.w += e1*vv[u].w;
                a2.x += e2*vv[u].x; a2.y += e2*vv[u].y; a2.z += e2*vv[u].z; a2.w += e2*vv[u].w;
                a3.x += e3*vv[u].x; a3.y += e3*vv[u].y; a3.z += e3*vv[u].z; a3.w += e3*vv[u].w;
            }
        }
    }

    // Cross-warp reduction in smem
    if (lane == 0) { wl[warp][0] = l0; wl[warp][1] = l1; wl[warp][2] = l2; wl[warp][3] = l3; }
    ((float4*)&red[warp][0][0])[lane] = a0;
    ((float4*)&red[warp][1][0])[lane] = a1;
    ((float4*)&red[warp][2][0])[lane] = a2;
    ((float4*)&red[warp][3][0])[lane] = a3;
    __syncthreads();

    const int d  = tid & 127;
    const int g0 = tid >> 7;
    float r0 = 0.f, r1 = 0.f;
    #pragma unroll
    for (int w = 0; w < NWARPS; w++) {
        r0 += red[w][g0][d];
        r1 += red[w][g0 + 2][d];
    }

    // Cross-partition combine via global atomics (REDG, no-return)
    const int hbase = s * NUM_HEADS + kv * GQ;
    atomicAdd(&g_oacc[(size_t)(hbase + g0)     * HD + d], r0);
    atomicAdd(&g_oacc[(size_t)(hbase + g0 + 2) * HD + d], r1);
    if (tid < GQ) {
        float L = 0.f;
        #pragma unroll
        for (int w = 0; w < NWARPS; w++) L += wl[w][tid];
        atomicAdd(&g_ol[hbase + tid], L);
    }
}

// Normalize: out[h, d] = g_oacc[h, d] / g_ol[h].  65536 float4's total.
__global__ __launch_bounds__(NTHREADS)
void normalize_kernel(float* __restrict__ out)
{
    const int i = blockIdx.x * NTHREADS + threadIdx.x;   // float4 index
    const int row = i >> 5;                              // (s, h)
    float4 a = ((const float4*)g_oacc)[i];
    const float inv = 1.0f / g_ol[row];
    a.x *= inv; a.y *= inv; a.z *= inv; a.w *= inv;
    ((float4*)out)[i] = a;
}

extern "C" void kernel_launch(void* const* d_in, const int* in_sizes, int n_in,
                              void* d_out, int out_size) {
    const float* query       = (const float*)d_in[0];
    const float* key_cache   = (const float*)d_in[1];
    const float* value_cache = (const float*)d_in[2];
    const float* scale       = (const float*)d_in[4];
    const int*   block_tab   = (const int*)  d_in[5];
    const int*   seq_lens    = (const int*)  d_in[6];
    const float* alibi       = (const float*)d_in[9];
    float* out = (float*)d_out;

    zero_acc_kernel<<<(NUM_SEQS * NUM_HEADS * HD + NTHREADS - 1) / NTHREADS, NTHREADS>>>();
    paged_attn_part_kernel<<<NUM_SEQS * KVH * NP, NTHREADS>>>(
        query, key_cache, value_cache, scale, block_tab, seq_lens, alibi);
    normalize_kernel<<<(NUM_SEQS * NUM_HEADS * HD / 4 + NTHREADS - 1) / NTHREADS, NTHREADS>>>(out);
}

// round 7
// speedup vs baseline: 1.1692x; 1.1410x over previous
#include <cuda_runtime.h>
#include <math.h>

#define NUM_SEQS   64
#define NUM_HEADS  32
#define KVH        8
#define GQ         4      // query heads per kv head
#define HD         128    // head size
#define BS         16     // paged block size
#define MAXL       2048
#define MAXB       128    // max blocks per seq
#define PART       128    // tokens per split-KV partition
#define NP         (MAXL / PART)   // 16
#define NTHREADS   256
#define NWARPS     8

// Split-KV scratch (device globals)
__device__ float g_pacc[NUM_SEQS * KVH * NP * GQ * HD];
__device__ float g_pl[NUM_SEQS * KVH * NP * GQ];

struct AccState {
    float4 a0, a1, a2, a3;
    float  l0, l1, l2, l3;
};

// Fused main loop over one 128-token partition. FULL=true means tmax==PART
// (all token slots valid): no bounds predicates anywhere on the hot path.
template <bool FULL>
__device__ __forceinline__ void run_mainloop(
    AccState& st, const float* __restrict__ kcache, const float* __restrict__ vcache,
    const int* __restrict__ blk, size_t kvbase, size_t kvstride,
    const float4 qr0, const float4 qr1, const float4 qr2, const float4 qr3,
    float slp0, float slp1, float slp2, float slp3,
    float relbase, int warp, int lane, int tmax)
{
    #pragma unroll
    for (int jb = 0; jb < 16; jb += 2) {
        const int tlA = warp + jb * NWARPS;
        const int tlB = tlA + NWARPS;
        const bool okA = FULL || (tlA < tmax);
        const bool okB = FULL || (tlB < tmax);

        float4 kA, kB, vA, vB;
        if (okA) {
            const size_t rowA = (size_t)blk[tlA >> 4] * kvstride + kvbase
                              + (size_t)(tlA & 15) * HD;
            kA = ((const float4*)(kcache + rowA))[lane];
            vA = ((const float4*)(vcache + rowA))[lane];
        }
        if (okB) {
            const size_t rowB = (size_t)blk[tlB >> 4] * kvstride + kvbase
                              + (size_t)(tlB & 15) * HD;
            kB = ((const float4*)(kcache + rowB))[lane];
            vB = ((const float4*)(vcache + rowB))[lane];
        }

        if (okA) {
            float p0 = qr0.x*kA.x + qr0.y*kA.y + qr0.z*kA.z + qr0.w*kA.w;
            float p1 = qr1.x*kA.x + qr1.y*kA.y + qr1.z*kA.z + qr1.w*kA.w;
            float p2 = qr2.x*kA.x + qr2.y*kA.y + qr2.z*kA.z + qr2.w*kA.w;
            float p3 = qr3.x*kA.x + qr3.y*kA.y + qr3.z*kA.z + qr3.w*kA.w;
            #pragma unroll
            for (int off = 16; off > 0; off >>= 1) {
                p0 += __shfl_xor_sync(0xffffffff, p0, off);
                p1 += __shfl_xor_sync(0xffffffff, p1, off);
                p2 += __shfl_xor_sync(0xffffffff, p2, off);
                p3 += __shfl_xor_sync(0xffffffff, p3, off);
            }
            const float rel = relbase + (float)tlA;
            const float e0 = __expf(p0 + slp0 * rel);
            const float e1 = __expf(p1 + slp1 * rel);
            const float e2 = __expf(p2 + slp2 * rel);
            const float e3 = __expf(p3 + slp3 * rel);
            st.l0 += e0; st.l1 += e1; st.l2 += e2; st.l3 += e3;
            st.a0.x += e0*vA.x; st.a0.y += e0*vA.y; st.a0.z += e0*vA.z; st.a0.w += e0*vA.w;
            st.a1.x += e1*vA.x; st.a1.y += e1*vA.y; st.a1.z += e1*vA.z; st.a1.w += e1*vA.w;
            st.a2.x += e2*vA.x; st.a2.y += e2*vA.y; st.a2.z += e2*vA.z; st.a2.w += e2*vA.w;
            st.a3.x += e3*vA.x; st.a3.y += e3*vA.y; st.a3.z += e3*vA.z; st.a3.w += e3*vA.w;
        }
        if (okB) {
            float p0 = qr0.x*kB.x + qr0.y*kB.y + qr0.z*kB.z + qr0.w*kB.w;
            float p1 = qr1.x*kB.x + qr1.y*kB.y + qr1.z*kB.z + qr1.w*kB.w;
            float p2 = qr2.x*kB.x + qr2.y*kB.y + qr2.z*kB.z + qr2.w*kB.w;
            float p3 = qr3.x*kB.x + qr3.y*kB.y + qr3.z*kB.z + qr3.w*kB.w;
            #pragma unroll
            for (int off = 16; off > 0; off >>= 1) {
                p0 += __shfl_xor_sync(0xffffffff, p0, off);
                p1 += __shfl_xor_sync(0xffffffff, p1, off);
                p2 += __shfl_xor_sync(0xffffffff, p2, off);
                p3 += __shfl_xor_sync(0xffffffff, p3, off);
            }
            const float rel = relbase + (float)tlB;
            const float e0 = __expf(p0 + slp0 * rel);
            const float e1 = __expf(p1 + slp1 * rel);
            const float e2 = __expf(p2 + slp2 * rel);
            const float e3 = __expf(p3 + slp3 * rel);
            st.l0 += e0; st.l1 += e1; st.l2 += e2; st.l3 += e3;
            st.a0.x += e0*vB.x; st.a0.y += e0*vB.y; st.a0.z += e0*vB.z; st.a0.w += e0*vB.w;
            st.a1.x += e1*vB.x; st.a1.y += e1*vB.y; st.a1.z += e1*vB.z; st.a1.w += e1*vB.w;
            st.a2.x += e2*vB.x; st.a2.y += e2*vB.y; st.a2.z += e2*vB.z; st.a2.w += e2*vB.w;
            st.a3.x += e3*vB.x; st.a3.y += e3*vB.y; st.a3.z += e3*vB.z; st.a3.w += e3*vB.w;
        }
    }
}

__global__ __launch_bounds__(NTHREADS)
void paged_attn_part_kernel(const float* __restrict__ q,
                            const float* __restrict__ kcache,
                            const float* __restrict__ vcache,
                            const float* __restrict__ scale_p,
                            const int*   __restrict__ btab,
                            const int*   __restrict__ seqlen,
                            const float* __restrict__ slopes)
{
    const int p    = blockIdx.x % NP;
    const int kv   = (blockIdx.x / NP) % KVH;
    const int s    = blockIdx.x / (NP * KVH);
    const int tid  = threadIdx.x;
    const int lane = tid & 31;
    const int warp = tid >> 5;

    const int len = seqlen[s];
    const int t0  = p * PART;
    if (t0 >= len) return;
    const int tmax = min(PART, len - t0);
    const float scale = scale_p[0];

    __shared__ float red[NWARPS][GQ][HD];   // 16 KB; stages Q at start
    __shared__ float wl[NWARPS][GQ];
    __shared__ int   blk[PART / BS];

    for (int i = tid; i < GQ * HD; i += NTHREADS)
        red[0][0][i] = q[(s * NUM_HEADS + kv * GQ) * HD + i] * scale;
    const int nblk = (tmax + BS - 1) >> 4;
    if (tid < nblk) blk[tid] = btab[s * MAXB + (t0 >> 4) + tid];
    __syncthreads();

    const float4 qr0 = ((const float4*)&red[0][0][0])[lane];
    const float4 qr1 = ((const float4*)&red[0][1][0])[lane];
    const float4 qr2 = ((const float4*)&red[0][2][0])[lane];
    const float4 qr3 = ((const float4*)&red[0][3][0])[lane];
    __syncthreads();

    const float slp0 = slopes[kv * GQ + 0];
    const float slp1 = slopes[kv * GQ + 1];
    const float slp2 = slopes[kv * GQ + 2];
    const float slp3 = slopes[kv * GQ + 3];
    const float relbase = (float)(t0 - (len - 1));

    const size_t kvbase   = (size_t)kv * BS * HD;
    const size_t kvstride = (size_t)KVH * BS * HD;

    AccState st;
    st.a0 = make_float4(0,0,0,0); st.a1 = make_float4(0,0,0,0);
    st.a2 = make_float4(0,0,0,0); st.a3 = make_float4(0,0,0,0);
    st.l0 = st.l1 = st.l2 = st.l3 = 0.f;

    if (tmax == PART) {
        run_mainloop<true >(st, kcache, vcache, blk, kvbase, kvstride,
                            qr0, qr1, qr2, qr3, slp0, slp1, slp2, slp3,
                            relbase, warp, lane, tmax);
    } else {
        run_mainloop<false>(st, kcache, vcache, blk, kvbase, kvstride,
                            qr0, qr1, qr2, qr3, slp0, slp1, slp2, slp3,
                            relbase, warp, lane, tmax);
    }

    // Cross-warp reduction in smem
    if (lane == 0) { wl[warp][0] = st.l0; wl[warp][1] = st.l1;
                     wl[warp][2] = st.l2; wl[warp][3] = st.l3; }
    ((float4*)&red[warp][0][0])[lane] = st.a0;
    ((float4*)&red[warp][1][0])[lane] = st.a1;
    ((float4*)&red[warp][2][0])[lane] = st.a2;
    ((float4*)&red[warp][3][0])[lane] = st.a3;
    __syncthreads();

    const int d  = tid & 127;
    const int g0 = tid >> 7;
    float r0 = 0.f, r1 = 0.f;
    #pragma unroll
    for (int w = 0; w < NWARPS; w++) {
        r0 += red[w][g0][d];
        r1 += red[w][g0 + 2][d];
    }

    const size_t pb = ((size_t)(s * KVH + kv) * NP + p) * GQ;
    g_pacc[(pb + g0)     * HD + d] = r0;
    g_pacc[(pb + g0 + 2) * HD + d] = r1;
    if (tid < GQ) {
        float L = 0.f;
        #pragma unroll
        for (int w = 0; w < NWARPS; w++) L += wl[w][tid];
        g_pl[pb + tid] = L;
    }
}

// Reduce: 512 threads = 16 warps = 4 heads x 4 partition-chunks.
__global__ __launch_bounds__(512)
void paged_attn_reduce_kernel(const int* __restrict__ seqlen,
                              float* __restrict__ out)
{
    const int s    = blockIdx.x / KVH;
    const int kv   = blockIdx.x % KVH;
    const int wid  = threadIdx.x >> 5;
    const int lane = threadIdx.x & 31;
    const int g    = wid & 3;
    const int c    = wid >> 2;

    __shared__ float4 so[4][GQ][32];
    __shared__ float  sl[4][GQ];

    const int len = seqlen[s];
    const int np  = (len + PART - 1) / PART;
    const size_t base = (size_t)(s * KVH + kv) * NP * GQ;

    float4 o = {0,0,0,0};
    float  L = 0.f;
    for (int p = c; p < np; p += 4) {
        const size_t idx = base + (size_t)p * GQ + g;
        const float4 a = ((const float4*)g_pacc)[idx * (HD/4) + lane];
        L += g_pl[idx];
        o.x += a.x; o.y += a.y; o.z += a.z; o.w += a.w;
    }
    so[c][g][lane] = o;
    if (lane == 0) sl[c][g] = L;
    __syncthreads();

    if (wid < GQ) {
        const int gg = wid;
        float4 r = so[0][gg][lane];
        const float4 r1 = so[1][gg][lane];
        const float4 r2 = so[2][gg][lane];
        const float4 r3 = so[3][gg][lane];
        r.x += r1.x + r2.x + r3.x;
        r.y += r1.y + r2.y + r3.y;
        r.z += r1.z + r2.z + r3.z;
        r.w += r1.w + r2.w + r3.w;
        const float inv = 1.0f / (sl[0][gg] + sl[1][gg] + sl[2][gg] + sl[3][gg]);
        r.x *= inv; r.y *= inv; r.z *= inv; r.w *= inv;
        ((float4*)out)[(size_t)(s * NUM_HEADS + kv * GQ + gg) * (HD/4) + lane] = r;
    }
}

extern "C" void kernel_launch(void* const* d_in, const int* in_sizes, int n_in,
                              void* d_out, int out_size) {
    const float* query       = (const float*)d_in[0];
    const float* key_cache   = (const float*)d_in[1];
    const float* value_cache = (const float*)d_in[2];
    const float* scale       = (const float*)d_in[4];
    const int*   block_tab   = (const int*)  d_in[5];
    const int*   seq_lens    = (const int*)  d_in[6];
    const float* alibi       = (const float*)d_in[9];
    float* out = (float*)d_out;

    paged_attn_part_kernel<<<NUM_SEQS * KVH * NP, NTHREADS>>>(
        query, key_cache, value_cache, scale, block_tab, seq_lens, alibi);
    paged_attn_reduce_kernel<<<NUM_SEQS * KVH, 512>>>(seq_lens, out);
}

// round 8
// speedup vs baseline: 1.2767x; 1.0919x over previous
#include <cuda_runtime.h>
#include <math.h>

#define NUM_SEQS   64
#define NUM_HEADS  32
#define KVH        8
#define GQ         4      // query heads per kv head
#define HD         128    // head size
#define BS         16     // paged block size
#define MAXL       2048
#define MAXB       128    // max blocks per seq
#define PART       128    // tokens per split-KV partition
#define NP         (MAXL / PART)   // 16
#define NTHREADS   256
#define NWARPS     8
#define FULLMASK   0xffffffffu

// Split-KV scratch (device globals)
__device__ float g_pacc[NUM_SEQS * KVH * NP * GQ * HD];
__device__ float g_pl[NUM_SEQS * KVH * NP * GQ];

struct AccState {
    float4 a0, a1, a2, a3;
    float  lsum;           // per-lane: sum of e for head (lane&3)
};

// One token: dot for 4 heads -> transposed butterfly (lane l ends with the
// COMPLETE score of head l&3) -> single exp/lane -> broadcast e0..e3 -> V FMA.
__device__ __forceinline__ void token_step(
    AccState& st, const float4 k4, const float4 v4,
    const float4 qr0, const float4 qr1, const float4 qr2, const float4 qr3,
    const float rel, const float slp_lane, const int lane)
{
    float p0 = qr0.x*k4.x + qr0.y*k4.y + qr0.z*k4.z + qr0.w*k4.w;
    float p1 = qr1.x*k4.x + qr1.y*k4.y + qr1.z*k4.z + qr1.w*k4.w;
    float p2 = qr2.x*k4.x + qr2.y*k4.y + qr2.z*k4.z + qr2.w*k4.w;
    float p3 = qr3.x*k4.x + qr3.y*k4.y + qr3.z*k4.z + qr3.w*k4.w;

    // Round 1 (offset 1): pair-swap heads {0,1} and {2,3}
    const bool b0 = (lane & 1);
    float x01 = b0 ? p1 : p0;
    float y01 = b0 ? p0 : p1;
    x01 += __shfl_xor_sync(FULLMASK, y01, 1);
    float x23 = b0 ? p3 : p2;
    float y23 = b0 ? p2 : p3;
    x23 += __shfl_xor_sync(FULLMASK, y23, 1);
    // Round 2 (offset 2): swap head-pairs
    const bool b1 = (lane & 2);
    float x = b1 ? x23 : x01;
    float y = b1 ? x01 : x23;
    x += __shfl_xor_sync(FULLMASK, y, 2);
    // Rounds 3-5: plain butterfly; every lane gets full sum of head (lane&3)
    x += __shfl_xor_sync(FULLMASK, x, 4);
    x += __shfl_xor_sync(FULLMASK, x, 8);
    x += __shfl_xor_sync(FULLMASK, x, 16);

    const float e = __expf(fmaf(slp_lane, rel, x));
    st.lsum += e;

    const float e0 = __shfl_sync(FULLMASK, e, 0);
    const float e1 = __shfl_sync(FULLMASK, e, 1);
    const float e2 = __shfl_sync(FULLMASK, e, 2);
    const float e3 = __shfl_sync(FULLMASK, e, 3);

    st.a0.x += e0*v4.x; st.a0.y += e0*v4.y; st.a0.z += e0*v4.z; st.a0.w += e0*v4.w;
    st.a1.x += e1*v4.x; st.a1.y += e1*v4.y; st.a1.z += e1*v4.z; st.a1.w += e1*v4.w;
    st.a2.x += e2*v4.x; st.a2.y += e2*v4.y; st.a2.z += e2*v4.z; st.a2.w += e2*v4.w;
    st.a3.x += e3*v4.x; st.a3.y += e3*v4.y; st.a3.z += e3*v4.z; st.a3.w += e3*v4.w;
}

template <bool FULL>
__device__ __forceinline__ void run_mainloop(
    AccState& st, const float* __restrict__ kcache, const float* __restrict__ vcache,
    const int* __restrict__ blk, size_t kvbase, size_t kvstride,
    const float4 qr0, const float4 qr1, const float4 qr2, const float4 qr3,
    const float slp_lane, const float relbase, int warp, int lane, int tmax)
{
    #pragma unroll
    for (int jb = 0; jb < 16; jb += 2) {
        const int tlA = warp + jb * NWARPS;
        const int tlB = tlA + NWARPS;
        const bool okA = FULL || (tlA < tmax);
        const bool okB = FULL || (tlB < tmax);

        float4 kA, kB, vA, vB;
        if (okA) {
            const size_t rowA = (size_t)blk[tlA >> 4] * kvstride + kvbase
                              + (size_t)(tlA & 15) * HD;
            kA = ((const float4*)(kcache + rowA))[lane];
            vA = ((const float4*)(vcache + rowA))[lane];
        }
        if (okB) {
            const size_t rowB = (size_t)blk[tlB >> 4] * kvstride + kvbase
                              + (size_t)(tlB & 15) * HD;
            kB = ((const float4*)(kcache + rowB))[lane];
            vB = ((const float4*)(vcache + rowB))[lane];
        }

        if (okA) token_step(st, kA, vA, qr0, qr1, qr2, qr3,
                            relbase + (float)tlA, slp_lane, lane);
        if (okB) token_step(st, kB, vB, qr0, qr1, qr2, qr3,
                            relbase + (float)tlB, slp_lane, lane);
    }
}

__global__ __launch_bounds__(NTHREADS)
void paged_attn_part_kernel(const float* __restrict__ q,
                            const float* __restrict__ kcache,
                            const float* __restrict__ vcache,
                            const float* __restrict__ scale_p,
                            const int*   __restrict__ btab,
                            const int*   __restrict__ seqlen,
                            const float* __restrict__ slopes)
{
    const int p    = blockIdx.x % NP;
    const int kv   = (blockIdx.x / NP) % KVH;
    const int s    = blockIdx.x / (NP * KVH);
    const int tid  = threadIdx.x;
    const int lane = tid & 31;
    const int warp = tid >> 5;

    const int len = seqlen[s];
    const int t0  = p * PART;
    if (t0 >= len) return;
    const int tmax = min(PART, len - t0);
    const float scale = scale_p[0];

    __shared__ float red[NWARPS][GQ][HD];   // 16 KB; stages Q at start
    __shared__ float wl[NWARPS][GQ];
    __shared__ int   blk[PART / BS];

    for (int i = tid; i < GQ * HD; i += NTHREADS)
        red[0][0][i] = q[(s * NUM_HEADS + kv * GQ) * HD + i] * scale;
    const int nblk = (tmax + BS - 1) >> 4;
    if (tid < nblk) blk[tid] = btab[s * MAXB + (t0 >> 4) + tid];
    __syncthreads();

    const float4 qr0 = ((const float4*)&red[0][0][0])[lane];
    const float4 qr1 = ((const float4*)&red[0][1][0])[lane];
    const float4 qr2 = ((const float4*)&red[0][2][0])[lane];
    const float4 qr3 = ((const float4*)&red[0][3][0])[lane];
    __syncthreads();

    const float slp_lane = slopes[kv * GQ + (lane & 3)];
    const float relbase  = (float)(t0 - (len - 1));

    const size_t kvbase   = (size_t)kv * BS * HD;
    const size_t kvstride = (size_t)KVH * BS * HD;

    AccState st;
    st.a0 = make_float4(0,0,0,0); st.a1 = make_float4(0,0,0,0);
    st.a2 = make_float4(0,0,0,0); st.a3 = make_float4(0,0,0,0);
    st.lsum = 0.f;

    if (tmax == PART) {
        run_mainloop<true >(st, kcache, vcache, blk, kvbase, kvstride,
                            qr0, qr1, qr2, qr3, slp_lane, relbase, warp, lane, tmax);
    } else {
        run_mainloop<false>(st, kcache, vcache, blk, kvbase, kvstride,
                            qr0, qr1, qr2, qr3, slp_lane, relbase, warp, lane, tmax);
    }

    // Cross-warp reduction in smem. Lanes 0-3 hold l sums for heads 0-3.
    if (lane < GQ) wl[warp][lane] = st.lsum;
    ((float4*)&red[warp][0][0])[lane] = st.a0;
    ((float4*)&red[warp][1][0])[lane] = st.a1;
    ((float4*)&red[warp][2][0])[lane] = st.a2;
    ((float4*)&red[warp][3][0])[lane] = st.a3;
    __syncthreads();

    const int d  = tid & 127;
    const int g0 = tid >> 7;
    float r0 = 0.f, r1 = 0.f;
    #pragma unroll
    for (int w = 0; w < NWARPS; w++) {
        r0 += red[w][g0][d];
        r1 += red[w][g0 + 2][d];
    }

    const size_t pb = ((size_t)(s * KVH + kv) * NP + p) * GQ;
    g_pacc[(pb + g0)     * HD + d] = r0;
    g_pacc[(pb + g0 + 2) * HD + d] = r1;
    if (tid < GQ) {
        float L = 0.f;
        #pragma unroll
        for (int w = 0; w < NWARPS; w++) L += wl[w][tid];
        g_pl[pb + tid] = L;
    }
}

// Reduce: 512 threads = 16 warps = 4 heads x 4 partition-chunks.
__global__ __launch_bounds__(512)
void paged_attn_reduce_kernel(const int* __restrict__ seqlen,
                              float* __restrict__ out)
{
    const int s    = blockIdx.x / KVH;
    const int kv   = blockIdx.x % KVH;
    const int wid  = threadIdx.x >> 5;
    const int lane = threadIdx.x & 31;
    const int g    = wid & 3;
    const int c    = wid >> 2;

    __shared__ float4 so[4][GQ][32];
    __shared__ float  sl[4][GQ];

    const int len = seqlen[s];
    const int np  = (len + PART - 1) / PART;
    const size_t base = (size_t)(s * KVH + kv) * NP * GQ;

    float4 o = {0,0,0,0};
    float  L = 0.f;
    for (int p = c; p < np; p += 4) {
        const size_t idx = base + (size_t)p * GQ + g;
        const float4 a = ((const float4*)g_pacc)[idx * (HD/4) + lane];
        L += g_pl[idx];
        o.x += a.x; o.y += a.y; o.z += a.z; o.w += a.w;
    }
    so[c][g][lane] = o;
    if (lane == 0) sl[c][g] = L;
    __syncthreads();

    if (wid < GQ) {
        const int gg = wid;
        float4 r = so[0][gg][lane];
        const float4 r1 = so[1][gg][lane];
        const float4 r2 = so[2][gg][lane];
        const float4 r3 = so[3][gg][lane];
        r.x += r1.x + r2.x + r3.x;
        r.y += r1.y + r2.y + r3.y;
        r.z += r1.z + r2.z + r3.z;
        r.w += r1.w + r2.w + r3.w;
        const float inv = 1.0f / (sl[0][gg] + sl[1][gg] + sl[2][gg] + sl[3][gg]);
        r.x *= inv; r.y *= inv; r.z *= inv; r.w *= inv;
        ((float4*)out)[(size_t)(s * NUM_HEADS + kv * GQ + gg) * (HD/4) + lane] = r;
    }
}

extern "C" void kernel_launch(void* const* d_in, const int* in_sizes, int n_in,
                              void* d_out, int out_size) {
    const float* query       = (const float*)d_in[0];
    const float* key_cache   = (const float*)d_in[1];
    const float* value_cache = (const float*)d_in[2];
    const float* scale       = (const float*)d_in[4];
    const int*   block_tab   = (const int*)  d_in[5];
    const int*   seq_lens    = (const int*)  d_in[6];
    const float* alibi       = (const float*)d_in[9];
    float* out = (float*)d_out;

    paged_attn_part_kernel<<<NUM_SEQS * KVH * NP, NTHREADS>>>(
        query, key_cache, value_cache, scale, block_tab, seq_lens, alibi);
    paged_attn_reduce_kernel<<<NUM_SEQS * KVH, 512>>>(seq_lens, out);
}

// round 9
// speedup vs baseline: 1.2998x; 1.0181x over previous
#include <cuda_runtime.h>
#include <math.h>

#define NUM_SEQS   64
#define NUM_HEADS  32
#define KVH        8
#define GQ         4      // query heads per kv head
#define HD         128    // head size
#define BS         16     // paged block size
#define MAXL       2048
#define MAXB       128    // max blocks per seq
#define PART       128    // tokens per split-KV partition
#define NP         (MAXL / PART)   // 16
#define NTHREADS   256
#define NWARPS     8
#define FULLMASK   0xffffffffu

// Split-KV scratch (device globals)
__device__ float g_pacc[NUM_SEQS * KVH * NP * GQ * HD];
__device__ float g_pl[NUM_SEQS * KVH * NP * GQ];

struct AccState {
    float4 a0, a1, a2, a3;
    float  lsum;           // per-lane: sum of e for head (lane&3)
};

// One token: dot for 4 heads -> transposed butterfly (lane l ends with the
// COMPLETE score of head l&3) -> single exp/lane -> broadcast e0..e3 -> V FMA.
__device__ __forceinline__ void token_step(
    AccState& st, const float4 k4, const float4 v4,
    const float4 qr0, const float4 qr1, const float4 qr2, const float4 qr3,
    const float rel, const float slp_lane, const int lane)
{
    float p0 = qr0.x*k4.x + qr0.y*k4.y + qr0.z*k4.z + qr0.w*k4.w;
    float p1 = qr1.x*k4.x + qr1.y*k4.y + qr1.z*k4.z + qr1.w*k4.w;
    float p2 = qr2.x*k4.x + qr2.y*k4.y + qr2.z*k4.z + qr2.w*k4.w;
    float p3 = qr3.x*k4.x + qr3.y*k4.y + qr3.z*k4.z + qr3.w*k4.w;

    // Round 1 (offset 1): pair-swap heads {0,1} and {2,3}
    const bool b0 = (lane & 1);
    float x01 = b0 ? p1 : p0;
    float y01 = b0 ? p0 : p1;
    x01 += __shfl_xor_sync(FULLMASK, y01, 1);
    float x23 = b0 ? p3 : p2;
    float y23 = b0 ? p2 : p3;
    x23 += __shfl_xor_sync(FULLMASK, y23, 1);
    // Round 2 (offset 2): swap head-pairs
    const bool b1 = (lane & 2);
    float x = b1 ? x23 : x01;
    float y = b1 ? x01 : x23;
    x += __shfl_xor_sync(FULLMASK, y, 2);
    // Rounds 3-5: plain butterfly; every lane gets full sum of head (lane&3)
    x += __shfl_xor_sync(FULLMASK, x, 4);
    x += __shfl_xor_sync(FULLMASK, x, 8);
    x += __shfl_xor_sync(FULLMASK, x, 16);

    const float e = __expf(fmaf(slp_lane, rel, x));
    st.lsum += e;

    const float e0 = __shfl_sync(FULLMASK, e, 0);
    const float e1 = __shfl_sync(FULLMASK, e, 1);
    const float e2 = __shfl_sync(FULLMASK, e, 2);
    const float e3 = __shfl_sync(FULLMASK, e, 3);

    st.a0.x += e0*v4.x; st.a0.y += e0*v4.y; st.a0.z += e0*v4.z; st.a0.w += e0*v4.w;
    st.a1.x += e1*v4.x; st.a1.y += e1*v4.y; st.a1.z += e1*v4.z; st.a1.w += e1*v4.w;
    st.a2.x += e2*v4.x; st.a2.y += e2*v4.y; st.a2.z += e2*v4.z; st.a2.w += e2*v4.w;
    st.a3.x += e3*v4.x; st.a3.y += e3*v4.y; st.a3.z += e3*v4.z; st.a3.w += e3*v4.w;
}

// FULL path: software pipeline with prefetch depth 1 (next token pair's
// K/V loads issued before current pair's compute).
__device__ __forceinline__ void run_mainloop_full(
    AccState& st, const float* __restrict__ kcache, const float* __restrict__ vcache,
    const int* __restrict__ blk, size_t kvbase, size_t kvstride,
    const float4 qr0, const float4 qr1, const float4 qr2, const float4 qr3,
    const float slp_lane, const float relbase, int warp, int lane)
{
    // row address for token slot tl (tl < PART, all valid)
    auto row_of = [&](int tl) -> size_t {
        return (size_t)blk[tl >> 4] * kvstride + kvbase + (size_t)(tl & 15) * HD;
    };

    const size_t r0 = row_of(warp);
    const size_t r1 = row_of(warp + NWARPS);
    float4 kA = ((const float4*)(kcache + r0))[lane];
    float4 vA = ((const float4*)(vcache + r0))[lane];
    float4 kB = ((const float4*)(kcache + r1))[lane];
    float4 vB = ((const float4*)(vcache + r1))[lane];

    #pragma unroll
    for (int jb = 0; jb < 16; jb += 2) {
        const int tlA = warp + jb * NWARPS;
        const int tlB = tlA + NWARPS;

        float4 kA2, vA2, kB2, vB2;
        if (jb < 14) {
            const size_t rA = row_of(tlA + 2 * NWARPS);
            const size_t rB = row_of(tlB + 2 * NWARPS);
            kA2 = ((const float4*)(kcache + rA))[lane];
            vA2 = ((const float4*)(vcache + rA))[lane];
            kB2 = ((const float4*)(kcache + rB))[lane];
            vB2 = ((const float4*)(vcache + rB))[lane];
        }

        token_step(st, kA, vA, qr0, qr1, qr2, qr3,
                   relbase + (float)tlA, slp_lane, lane);
        token_step(st, kB, vB, qr0, qr1, qr2, qr3,
                   relbase + (float)tlB, slp_lane, lane);

        kA = kA2; vA = vA2; kB = kB2; vB = vB2;
    }
}

// Partial path (last partition of each sequence): R8's guarded loop.
__device__ __forceinline__ void run_mainloop_partial(
    AccState& st, const float* __restrict__ kcache, const float* __restrict__ vcache,
    const int* __restrict__ blk, size_t kvbase, size_t kvstride,
    const float4 qr0, const float4 qr1, const float4 qr2, const float4 qr3,
    const float slp_lane, const float relbase, int warp, int lane, int tmax)
{
    #pragma unroll
    for (int jb = 0; jb < 16; jb += 2) {
        const int tlA = warp + jb * NWARPS;
        const int tlB = tlA + NWARPS;
        const bool okA = tlA < tmax;
        const bool okB = tlB < tmax;

        float4 kA, kB, vA, vB;
        if (okA) {
            const size_t rowA = (size_t)blk[tlA >> 4] * kvstride + kvbase
                              + (size_t)(tlA & 15) * HD;
            kA = ((const float4*)(kcache + rowA))[lane];
            vA = ((const float4*)(vcache + rowA))[lane];
        }
        if (okB) {
            const size_t rowB = (size_t)blk[tlB >> 4] * kvstride + kvbase
                              + (size_t)(tlB & 15) * HD;
            kB = ((const float4*)(kcache + rowB))[lane];
            vB = ((const float4*)(vcache + rowB))[lane];
        }

        if (okA) token_step(st, kA, vA, qr0, qr1, qr2, qr3,
                            relbase + (float)tlA, slp_lane, lane);
        if (okB) token_step(st, kB, vB, qr0, qr1, qr2, qr3,
                            relbase + (float)tlB, slp_lane, lane);
    }
}

__global__ __launch_bounds__(NTHREADS)
void paged_attn_part_kernel(const float* __restrict__ q,
                            const float* __restrict__ kcache,
                            const float* __restrict__ vcache,
                            const float* __restrict__ scale_p,
                            const int*   __restrict__ btab,
                            const int*   __restrict__ seqlen,
                            const float* __restrict__ slopes)
{
    const int p    = blockIdx.x % NP;
    const int kv   = (blockIdx.x / NP) % KVH;
    const int s    = blockIdx.x / (NP * KVH);
    const int tid  = threadIdx.x;
    const int lane = tid & 31;
    const int warp = tid >> 5;

    const int len = seqlen[s];
    const int t0  = p * PART;
    if (t0 >= len) return;
    const int tmax = min(PART, len - t0);
    const float scale = scale_p[0];

    __shared__ float red[NWARPS][GQ][HD];   // 16 KB; stages Q at start
    __shared__ float wl[NWARPS][GQ];
    __shared__ int   blk[PART / BS];

    for (int i = tid; i < GQ * HD; i += NTHREADS)
        red[0][0][i] = q[(s * NUM_HEADS + kv * GQ) * HD + i] * scale;
    const int nblk = (tmax + BS - 1) >> 4;
    if (tid < nblk) blk[tid] = btab[s * MAXB + (t0 >> 4) + tid];
    __syncthreads();

    const float4 qr0 = ((const float4*)&red[0][0][0])[lane];
    const float4 qr1 = ((const float4*)&red[0][1][0])[lane];
    const float4 qr2 = ((const float4*)&red[0][2][0])[lane];
    const float4 qr3 = ((const float4*)&red[0][3][0])[lane];
    __syncthreads();

    const float slp_lane = slopes[kv * GQ + (lane & 3)];
    const float relbase  = (float)(t0 - (len - 1));

    const size_t kvbase   = (size_t)kv * BS * HD;
    const size_t kvstride = (size_t)KVH * BS * HD;

    AccState st;
    st.a0 = make_float4(0,0,0,0); st.a1 = make_float4(0,0,0,0);
    st.a2 = make_float4(0,0,0,0); st.a3 = make_float4(0,0,0,0);
    st.lsum = 0.f;

    if (tmax == PART) {
        run_mainloop_full(st, kcache, vcache, blk, kvbase, kvstride,
                          qr0, qr1, qr2, qr3, slp_lane, relbase, warp, lane);
    } else {
        run_mainloop_partial(st, kcache, vcache, blk, kvbase, kvstride,
                             qr0, qr1, qr2, qr3, slp_lane, relbase, warp, lane, tmax);
    }

    // Cross-warp reduction in smem. Lanes 0-3 hold l sums for heads 0-3.
    if (lane < GQ) wl[warp][lane] = st.lsum;
    ((float4*)&red[warp][0][0])[lane] = st.a0;
    ((float4*)&red[warp][1][0])[lane] = st.a1;
    ((float4*)&red[warp][2][0])[lane] = st.a2;
    ((float4*)&red[warp][3][0])[lane] = st.a3;
    __syncthreads();

    const int d  = tid & 127;
    const int g0 = tid >> 7;
    float r0 = 0.f, r1 = 0.f;
    #pragma unroll
    for (int w = 0; w < NWARPS; w++) {
        r0 += red[w][g0][d];
        r1 += red[w][g0 + 2][d];
    }

    const size_t pb = ((size_t)(s * KVH + kv) * NP + p) * GQ;
    g_pacc[(pb + g0)     * HD + d] = r0;
    g_pacc[(pb + g0 + 2) * HD + d] = r1;
    if (tid < GQ) {
        float L = 0.f;
        #pragma unroll
        for (int w = 0; w < NWARPS; w++) L += wl[w][tid];
        g_pl[pb + tid] = L;
    }
}

// Reduce: 512 threads = 16 warps = 4 heads x 4 partition-chunks.
__global__ __launch_bounds__(512)
void paged_attn_reduce_kernel(const int* __restrict__ seqlen,
                              float* __restrict__ out)
{
    const int s    = blockIdx.x / KVH;
    const int kv   = blockIdx.x % KVH;
    const int wid  = threadIdx.x >> 5;
    const int lane = threadIdx.x & 31;
    const int g    = wid & 3;
    const int c    = wid >> 2;

    __shared__ float4 so[4][GQ][32];
    __shared__ float  sl[4][GQ];

    const int len = seqlen[s];
    const int np  = (len + PART - 1) / PART;
    const size_t base = (size_t)(s * KVH + kv) * NP * GQ;

    float4 o = {0,0,0,0};
    float  L = 0.f;
    for (int p = c; p < np; p += 4) {
        const size_t idx = base + (size_t)p * GQ + g;
        const float4 a = ((const float4*)g_pacc)[idx * (HD/4) + lane];
        L += g_pl[idx];
        o.x += a.x; o.y += a.y; o.z += a.z; o.w += a.w;
    }
    so[c][g][lane] = o;
    if (lane == 0) sl[c][g] = L;
    __syncthreads();

    if (wid < GQ) {
        const int gg = wid;
        float4 r = so[0][gg][lane];
        const float4 r1 = so[1][gg][lane];
        const float4 r2 = so[2][gg][lane];
        const float4 r3 = so[3][gg][lane];
        r.x += r1.x + r2.x + r3.x;
        r.y += r1.y + r2.y + r3.y;
        r.z += r1.z + r2.z + r3.z;
        r.w += r1.w + r2.w + r3.w;
        const float inv = 1.0f / (sl[0][gg] + sl[1][gg] + sl[2][gg] + sl[3][gg]);
        r.x *= inv; r.y *= inv; r.z *= inv; r.w *= inv;
        ((float4*)out)[(size_t)(s * NUM_HEADS + kv * GQ + gg) * (HD/4) + lane] = r;
    }
}

extern "C" void kernel_launch(void* const* d_in, const int* in_sizes, int n_in,
                              void* d_out, int out_size) {
    const float* query       = (const float*)d_in[0];
    const float* key_cache   = (const float*)d_in[1];
    const float* value_cache = (const float*)d_in[2];
    const float* scale       = (const float*)d_in[4];
    const int*   block_tab   = (const int*)  d_in[5];
    const int*   seq_lens    = (const int*)  d_in[6];
    const float* alibi       = (const float*)d_in[9];
    float* out = (float*)d_out;

    paged_attn_part_kernel<<<NUM_SEQS * KVH * NP, NTHREADS>>>(
        query, key_cache, value_cache, scale, block_tab, seq_lens, alibi);
    paged_attn_reduce_kernel<<<NUM_SEQS * KVH, 512>>>(seq_lens, out);
}